// round 9
// baseline (speedup 1.0000x reference)
#include <cuda_runtime.h>

#define BB   8
#define NN   4096
#define DIN  128
#define DOUT 256
#define SS   1024
#define KKNN 16
#define MTOT (BB*SS*KKNN)
#define XYZ_OFF (BB*SS*DOUT)

__device__ float  g_h[BB*NN*DOUT];
__device__ int    g_knn[MTOT];
__device__ double g_sum[DOUT];
__device__ double g_sumsq[DOUT];

// ---------------------------------------------------------------------------
// K1: blocks 0..7 = FPS (one batch each); blocks 8.. = exact-fp32 SGEMM.
// ---------------------------------------------------------------------------
__global__ __launch_bounds__(1024) void k1_fps_gemm(
    const float* __restrict__ feat, const float* __restrict__ xyz,
    const float* __restrict__ W, const float* __restrict__ bias,
    float* __restrict__ out)
{
    extern __shared__ float sm[];
    const int tid = threadIdx.x;
    const int bid = blockIdx.x;

    if (bid < BB) {
        float* sx = sm;  float* sy = sm + NN;  float* sz = sm + 2*NN;
        unsigned* wval = (unsigned*)(sm + 3*NN);
        unsigned* widx = wval + 32;
        unsigned* win  = widx + 32;

        const float* bx = xyz + (size_t)bid * NN * 3;
        float px[4], py[4], pz[4], dist[4];
        #pragma unroll
        for (int j = 0; j < 4; j++) {
            int i = j*1024 + tid;
            float x = bx[i*3+0], y = bx[i*3+1], z = bx[i*3+2];
            px[j]=x; py[j]=y; pz[j]=z;
            sx[i]=x; sy[i]=y; sz[i]=z;
            dist[j] = 1e10f;
        }
        __syncthreads();
        float lx = sx[0], ly = sy[0], lz = sz[0];
        if (tid == 0) {
            float* o = out + XYZ_OFF + (size_t)(bid*SS)*3;
            o[0]=lx; o[1]=ly; o[2]=lz;
        }
        const int lane = tid & 31, wid = tid >> 5;

        for (int s = 1; s < SS; s++) {
            float bv; unsigned bi;
            #pragma unroll
            for (int j = 0; j < 4; j++) {
                float dx = px[j]-lx, dy = py[j]-ly, dz = pz[j]-lz;
                float d  = __fadd_rn(__fadd_rn(__fmul_rn(dx,dx),
                                               __fmul_rn(dy,dy)),
                                               __fmul_rn(dz,dz));
                float nd = fminf(dist[j], d);
                dist[j] = nd;
                if (j == 0) { bv = nd; bi = (unsigned)tid; }
                else if (nd > bv) { bv = nd; bi = (unsigned)(j*1024 + tid); }
            }
            unsigned uv  = __float_as_uint(bv);
            unsigned m   = __reduce_max_sync(0xffffffffu, uv);
            unsigned cnd = (uv == m) ? bi : 0xffffffffu;
            unsigned mi  = __reduce_min_sync(0xffffffffu, cnd);
            if (lane == 0) { wval[wid] = m; widx[wid] = mi; }
            __syncthreads();
            if (tid < 32) {
                unsigned v = wval[tid], ii = widx[tid];
                unsigned m2 = __reduce_max_sync(0xffffffffu, v);
                unsigned c2 = (v == m2) ? ii : 0xffffffffu;
                unsigned w2 = __reduce_min_sync(0xffffffffu, c2);
                if (tid == 0) {
                    *win = w2;
                    float* o = out + XYZ_OFF + (size_t)(bid*SS + s)*3;
                    o[0]=sx[w2]; o[1]=sy[w2]; o[2]=sz[w2];
                }
            }
            __syncthreads();
            unsigned wn = *win;
            lx = sx[wn]; ly = sy[wn]; lz = sz[wn];
        }
    } else {
        const int g = bid - BB;
        const int rowBase = (g & 255) * 128;
        const int colBase = (g >> 8) * 128;
        float* As = sm;              // [16][132]
        float* Bs = sm + 16*132;     // [16][132]
        const int l = tid & 31, w = tid >> 5;
        const int tm = l*4, tn = w*4;
        float acc[4][4];
        #pragma unroll
        for (int i=0;i<4;i++)
            #pragma unroll
            for (int j=0;j<4;j++) acc[i][j] = 0.f;

        for (int kc = 0; kc < DIN; kc += 16) {
            if (tid < 512) {
                int r = tid >> 2, q = tid & 3;
                float4 v = *(const float4*)(feat + (size_t)(rowBase + r)*DIN + kc + q*4);
                As[(q*4+0)*132 + r] = v.x;
                As[(q*4+1)*132 + r] = v.y;
                As[(q*4+2)*132 + r] = v.z;
                As[(q*4+3)*132 + r] = v.w;
            } else {
                int t2 = tid - 512; int c = t2 >> 2, q = t2 & 3;
                float4 v = *(const float4*)(W + (size_t)(colBase + c)*DIN + kc + q*4);
                Bs[(q*4+0)*132 + c] = v.x;
                Bs[(q*4+1)*132 + c] = v.y;
                Bs[(q*4+2)*132 + c] = v.z;
                Bs[(q*4+3)*132 + c] = v.w;
            }
            __syncthreads();
            #pragma unroll
            for (int kk = 0; kk < 16; kk++) {
                float4 a  = *(const float4*)(As + kk*132 + tm);
                float4 bb = *(const float4*)(Bs + kk*132 + tn);
                acc[0][0] += a.x*bb.x; acc[0][1] += a.x*bb.y; acc[0][2] += a.x*bb.z; acc[0][3] += a.x*bb.w;
                acc[1][0] += a.y*bb.x; acc[1][1] += a.y*bb.y; acc[1][2] += a.y*bb.z; acc[1][3] += a.y*bb.w;
                acc[2][0] += a.z*bb.x; acc[2][1] += a.z*bb.y; acc[2][2] += a.z*bb.z; acc[2][3] += a.z*bb.w;
                acc[3][0] += a.w*bb.x; acc[3][1] += a.w*bb.y; acc[3][2] += a.w*bb.z; acc[3][3] += a.w*bb.w;
            }
            __syncthreads();
        }
        #pragma unroll
        for (int i = 0; i < 4; i++) {
            int row = rowBase + tm + i;
            float4 o;
            o.x = acc[i][0] + bias[colBase+tn+0];
            o.y = acc[i][1] + bias[colBase+tn+1];
            o.z = acc[i][2] + bias[colBase+tn+2];
            o.w = acc[i][3] + bias[colBase+tn+3];
            *(float4*)(g_h + (size_t)row*DOUT + colBase + tn) = o;
        }
    }
}

// ---------------------------------------------------------------------------
// K2: KNN. fp32 expansion-form prefilter (top-16 per 2048-half), then the 32
// surviving candidates are re-ranked in EXACT fp64 difference-form — this
// removes the deterministic ~2.7e-7 cancellation error of the fp32 expansion
// that causes the boundary flips vs the reference.
// SMEM: sx,sy,sz,p2 (64KB) + md/mi merge buffers (32KB) = 96KB.
// ---------------------------------------------------------------------------
__global__ __launch_bounds__(256) void k2_knn(
    const float* __restrict__ xyz, const float* __restrict__ out)
{
    extern __shared__ float sm[];
    float* sx = sm;  float* sy = sm + NN;  float* sz = sm + 2*NN;  float* p2 = sm + 3*NN;
    float* md = sm + 4*NN;               // [256][16]
    int*   mi = (int*)(md + 256*16);     // [256][16]
    const int tid = threadIdx.x;
    const int b = blockIdx.x >> 3;
    const int chunk = blockIdx.x & 7;

    if (blockIdx.x == 0) { g_sum[tid] = 0.0; g_sumsq[tid] = 0.0; }

    const float* bx = xyz + (size_t)b * NN * 3;
    for (int i = tid; i < NN; i += 256) {
        float x = bx[i*3], y = bx[i*3+1], z = bx[i*3+2];
        sx[i]=x; sy[i]=y; sz[i]=z;
        p2[i] = __fmaf_rn(z, z, __fmaf_rn(y, y, __fmul_rn(x, x)));
    }
    __syncthreads();

    const int q = chunk*128 + (tid & 127);
    const int half = tid >> 7;
    const float* qp = out + XYZ_OFF + (size_t)(b*SS + q)*3;
    const float qx = qp[0], qy = qp[1], qz = qp[2];
    const float q2 = __fmaf_rn(qz, qz, __fmaf_rn(qy, qy, __fmul_rn(qx, qx)));

    float dk[16]; int ik[16];
    #pragma unroll
    for (int j = 0; j < 16; j++) { dk[j] = 3.4e38f; ik[j] = 0; }

    const int i0 = half * 2048;
    #pragma unroll 2
    for (int i = i0; i < i0 + 2048; i++) {
        float dot = __fmaf_rn(qz, sz[i], __fmaf_rn(qy, sy[i], __fmul_rn(qx, sx[i])));
        float d   = __fmaf_rn(-2.0f, dot, __fadd_rn(q2, p2[i]));
        if (d < dk[15]) {
            dk[15] = d; ik[15] = i;
            #pragma unroll
            for (int j = 15; j > 0; --j) {
                if (dk[j] < dk[j-1]) {
                    float td = dk[j]; dk[j] = dk[j-1]; dk[j-1] = td;
                    int   ti = ik[j]; ik[j] = ik[j-1]; ik[j-1] = ti;
                } else break;
            }
        }
    }
    #pragma unroll
    for (int j = 0; j < 16; j++) { md[tid*16+j] = dk[j]; mi[tid*16+j] = ik[j]; }
    __syncthreads();

    if (tid < 128) {
        // 32 candidates: my half's 16 + partner half's 16 (disjoint ranges)
        int cand[32];
        #pragma unroll
        for (int j = 0; j < 16; j++) {
            cand[j]    = mi[tid*16 + j];
            cand[16+j] = mi[(tid+128)*16 + j];
        }
        // exact fp64 difference-form re-rank (sx/sy/sz still live)
        const double qdx = (double)qx, qdy = (double)qy, qdz = (double)qz;
        double dd[32];
        #pragma unroll
        for (int j = 0; j < 32; j++) {
            int c = cand[j];
            double ax = (double)sx[c] - qdx;
            double ay = (double)sy[c] - qdy;
            double az = (double)sz[c] - qdz;
            dd[j] = ax*ax + ay*ay + az*az;
        }
        int* dst = g_knn + (size_t)(b*SS + q)*KKNN;
        // selection of 16 smallest by (d2, index)
        for (int s = 0; s < 16; s++) {
            int best = s;
            for (int j = s+1; j < 32; j++) {
                if (dd[j] < dd[best] ||
                    (dd[j] == dd[best] && cand[j] < cand[best])) best = j;
            }
            double td = dd[best]; dd[best] = dd[s]; dd[s] = td;
            int    tc = cand[best]; cand[best] = cand[s]; cand[s] = tc;
            dst[s] = tc;
        }
    }
}

// ---------------------------------------------------------------------------
// K3: BN statistics over gathered rows (multiplicity-weighted), fp64 acc.
// ---------------------------------------------------------------------------
__global__ __launch_bounds__(256) void k3_stats()
{
    __shared__ int sbase[512];
    const int tid = threadIdx.x;
    const int r0 = blockIdx.x * 512;
    for (int j = tid; j < 512; j += 256) {
        int r = r0 + j;
        int b = r >> 14;
        sbase[j] = (b*NN + g_knn[r]) * DOUT;
    }
    __syncthreads();
    double s0=0,s1=0,s2=0,s3=0, q0=0,q1=0,q2=0,q3=0;
    for (int j = 0; j < 512; j += 4) {
        float v0 = g_h[(size_t)sbase[j]   + tid];
        float v1 = g_h[(size_t)sbase[j+1] + tid];
        float v2 = g_h[(size_t)sbase[j+2] + tid];
        float v3 = g_h[(size_t)sbase[j+3] + tid];
        s0 += v0; s1 += v1; s2 += v2; s3 += v3;
        q0 = fma((double)v0,(double)v0,q0);
        q1 = fma((double)v1,(double)v1,q1);
        q2 = fma((double)v2,(double)v2,q2);
        q3 = fma((double)v3,(double)v3,q3);
    }
    atomicAdd(&g_sum[tid],   (s0+s1)+(s2+s3));
    atomicAdd(&g_sumsq[tid], (q0+q1)+(q2+q3));
}

// ---------------------------------------------------------------------------
// K4: per-(b,s) max over K, fused BN affine + ReLU (monotone per channel).
// ---------------------------------------------------------------------------
__global__ __launch_bounds__(256) void k4_final(
    const float* __restrict__ gamma, const float* __restrict__ beta,
    float* __restrict__ out)
{
    __shared__ int hid[16];
    const int bs = blockIdx.x;
    const int tid = threadIdx.x;
    if (tid < 16) {
        int b = bs >> 10;
        hid[tid] = (b*NN + g_knn[(size_t)bs*KKNN + tid]) * DOUT;
    }
    __syncthreads();
    float mean = (float)(g_sum[tid] * (1.0 / MTOT));
    float var  = (float)(g_sumsq[tid] * (1.0 / MTOT)
                         - (g_sum[tid]*(1.0/MTOT))*(g_sum[tid]*(1.0/MTOT)));
    float rinv = 1.0f / sqrtf(__fadd_rn(var, 1e-5f));
    float ga = gamma[tid], be = beta[tid];
    float m;
    if (ga >= 0.f) {
        m = -3.4e38f;
        #pragma unroll
        for (int k = 0; k < 16; k++) m = fmaxf(m, g_h[(size_t)hid[k] + tid]);
    } else {
        m = 3.4e38f;
        #pragma unroll
        for (int k = 0; k < 16; k++) m = fminf(m, g_h[(size_t)hid[k] + tid]);
    }
    float val = __fadd_rn(__fmul_rn(__fmul_rn(ga, __fsub_rn(m, mean)), rinv), be);
    out[(size_t)bs*DOUT + tid] = fmaxf(val, 0.f);
}

// ---------------------------------------------------------------------------
extern "C" void kernel_launch(void* const* d_in, const int* in_sizes, int n_in,
                              void* d_out, int out_size)
{
    (void)in_sizes; (void)n_in; (void)out_size;
    const float* feat  = (const float*)d_in[0];
    const float* xyz   = (const float*)d_in[1];
    const float* W     = (const float*)d_in[2];
    const float* bias  = (const float*)d_in[3];
    const float* gamma = (const float*)d_in[4];
    const float* beta  = (const float*)d_in[5];
    float* out = (float*)d_out;

    const int sm1 = (3*NN + 80) * 4;           // FPS / GEMM shared
    const int sm2 = 4*NN*4 + 256*16*8;         // xyz SoA + p2 + merge buffers (96KB)
    cudaFuncSetAttribute(k1_fps_gemm, cudaFuncAttributeMaxDynamicSharedMemorySize, sm1);
    cudaFuncSetAttribute(k2_knn,      cudaFuncAttributeMaxDynamicSharedMemorySize, sm2);

    k1_fps_gemm<<<BB + 512, 1024, sm1>>>(feat, xyz, W, bias, out);
    k2_knn<<<64, 256, sm2>>>(xyz, out);
    k3_stats<<<256, 256>>>();
    k4_final<<<BB*SS, 256>>>(gamma, beta, out);
}

// round 10
// speedup vs baseline: 1.0160x; 1.0160x over previous
#include <cuda_runtime.h>

#define BB   8
#define NN   4096
#define DIN  128
#define DOUT 256
#define SS   1024
#define KKNN 16
#define MTOT (BB*SS*KKNN)
#define XYZ_OFF (BB*SS*DOUT)

__device__ float  g_h[BB*NN*DOUT];      // h for all points (33.5MB, L2-resident)
__device__ float  g_hmax[BB*SS*DOUT];   // per-sample max over K (8MB)
__device__ int    g_knn[MTOT];
__device__ double g_sum[DOUT];
__device__ double g_sumsq[DOUT];

// ---------------------------------------------------------------------------
// K1: blocks 0..7 = FPS (one batch each); blocks 8.. = exact-fp32 SGEMM.
// FPS: ONE barrier/iter — warp winners packed u64 in double-buffered SMEM,
// final 32-way reduce done redundantly by every warp via REDUX.
// Distance arithmetic is bit-frozen (3 sub, 3 mul, 2 add, fmin; no FMA).
// ---------------------------------------------------------------------------
__global__ __launch_bounds__(1024) void k1_fps_gemm(
    const float* __restrict__ feat, const float* __restrict__ xyz,
    const float* __restrict__ W, const float* __restrict__ bias,
    float* __restrict__ out)
{
    extern __shared__ float sm[];
    const int tid = threadIdx.x;
    const int bid = blockIdx.x;

    if (bid < BB) {
        float* sx = sm;  float* sy = sm + NN;  float* sz = sm + 2*NN;
        unsigned long long* wpack = (unsigned long long*)(sm + 3*NN); // [2][32]

        const float* bx = xyz + (size_t)bid * NN * 3;
        float px[4], py[4], pz[4], dist[4];
        #pragma unroll
        for (int j = 0; j < 4; j++) {
            int i = j*1024 + tid;
            float x = bx[i*3+0], y = bx[i*3+1], z = bx[i*3+2];
            px[j]=x; py[j]=y; pz[j]=z;
            sx[i]=x; sy[i]=y; sz[i]=z;
            dist[j] = 1e10f;
        }
        __syncthreads();
        float lx = sx[0], ly = sy[0], lz = sz[0];
        if (tid == 0) {
            float* o = out + XYZ_OFF + (size_t)(bid*SS)*3;
            o[0]=lx; o[1]=ly; o[2]=lz;
        }
        const int lane = tid & 31, wid = tid >> 5;

        for (int s = 1; s < SS; s++) {
            // ---- exact distance update (frozen arithmetic) ----
            float nd[4];
            #pragma unroll
            for (int j = 0; j < 4; j++) {
                float dx = px[j]-lx, dy = py[j]-ly, dz = pz[j]-lz;
                float d  = __fadd_rn(__fadd_rn(__fmul_rn(dx,dx),
                                               __fmul_rn(dy,dy)),
                                               __fmul_rn(dz,dz));
                nd[j] = fminf(dist[j], d);
                dist[j] = nd[j];
            }
            // thread-best: max value, min index (indices j*1024+tid ascending in j)
            float bv = fmaxf(fmaxf(nd[0], nd[1]), fmaxf(nd[2], nd[3]));
            unsigned bi = (nd[0]==bv) ? (unsigned)tid
                        : (nd[1]==bv) ? (unsigned)(1024+tid)
                        : (nd[2]==bv) ? (unsigned)(2048+tid)
                                      : (unsigned)(3072+tid);
            // warp reduce (argmax, min-index tiebreak)
            unsigned uv  = __float_as_uint(bv);
            unsigned m   = __reduce_max_sync(0xffffffffu, uv);
            unsigned cnd = (uv == m) ? bi : 0xffffffffu;
            unsigned mi  = __reduce_min_sync(0xffffffffu, cnd);
            const int buf = (s & 1) << 5;
            if (lane == 0) wpack[buf + wid] = ((unsigned long long)m << 32) | mi;
            __syncthreads();
            // every warp redundantly reduces the 32 warp winners
            unsigned long long pk = wpack[buf + lane];
            unsigned v  = (unsigned)(pk >> 32);
            unsigned ii = (unsigned)pk;
            unsigned m2 = __reduce_max_sync(0xffffffffu, v);
            unsigned c2 = (v == m2) ? ii : 0xffffffffu;
            unsigned w2 = __reduce_min_sync(0xffffffffu, c2);
            lx = sx[w2]; ly = sy[w2]; lz = sz[w2];
            if (tid == 0) {
                float* o = out + XYZ_OFF + (size_t)(bid*SS + s)*3;
                o[0]=lx; o[1]=ly; o[2]=lz;
            }
        }
    } else {
        // -------- SGEMM: h = feat @ W^T + b, exact fp32 --------
        const int g = bid - BB;
        const int rowBase = (g & 255) * 128;
        const int colBase = (g >> 8) * 128;
        float* As = sm;              // [16][132]
        float* Bs = sm + 16*132;     // [16][132]
        const int l = tid & 31, w = tid >> 5;
        const int tm = l*4, tn = w*4;
        float acc[4][4];
        #pragma unroll
        for (int i=0;i<4;i++)
            #pragma unroll
            for (int j=0;j<4;j++) acc[i][j] = 0.f;

        for (int kc = 0; kc < DIN; kc += 16) {
            if (tid < 512) {
                int r = tid >> 2, q = tid & 3;
                float4 v = *(const float4*)(feat + (size_t)(rowBase + r)*DIN + kc + q*4);
                As[(q*4+0)*132 + r] = v.x;
                As[(q*4+1)*132 + r] = v.y;
                As[(q*4+2)*132 + r] = v.z;
                As[(q*4+3)*132 + r] = v.w;
            } else {
                int t2 = tid - 512; int c = t2 >> 2, q = t2 & 3;
                float4 v = *(const float4*)(W + (size_t)(colBase + c)*DIN + kc + q*4);
                Bs[(q*4+0)*132 + c] = v.x;
                Bs[(q*4+1)*132 + c] = v.y;
                Bs[(q*4+2)*132 + c] = v.z;
                Bs[(q*4+3)*132 + c] = v.w;
            }
            __syncthreads();
            #pragma unroll
            for (int kk = 0; kk < 16; kk++) {
                float4 a  = *(const float4*)(As + kk*132 + tm);
                float4 bb = *(const float4*)(Bs + kk*132 + tn);
                acc[0][0] += a.x*bb.x; acc[0][1] += a.x*bb.y; acc[0][2] += a.x*bb.z; acc[0][3] += a.x*bb.w;
                acc[1][0] += a.y*bb.x; acc[1][1] += a.y*bb.y; acc[1][2] += a.y*bb.z; acc[1][3] += a.y*bb.w;
                acc[2][0] += a.z*bb.x; acc[2][1] += a.z*bb.y; acc[2][2] += a.z*bb.z; acc[2][3] += a.z*bb.w;
                acc[3][0] += a.w*bb.x; acc[3][1] += a.w*bb.y; acc[3][2] += a.w*bb.z; acc[3][3] += a.w*bb.w;
            }
            __syncthreads();
        }
        #pragma unroll
        for (int i = 0; i < 4; i++) {
            int row = rowBase + tm + i;
            float4 o;
            o.x = acc[i][0] + bias[colBase+tn+0];
            o.y = acc[i][1] + bias[colBase+tn+1];
            o.z = acc[i][2] + bias[colBase+tn+2];
            o.w = acc[i][3] + bias[colBase+tn+3];
            *(float4*)(g_h + (size_t)row*DOUT + colBase + tn) = o;
        }
    }
}

// ---------------------------------------------------------------------------
// K2: KNN — fp32 expansion prefilter, fp64 difference-form re-rank (exact).
// ---------------------------------------------------------------------------
__global__ __launch_bounds__(256) void k2_knn(
    const float* __restrict__ xyz, const float* __restrict__ out)
{
    extern __shared__ float sm[];
    float* sx = sm;  float* sy = sm + NN;  float* sz = sm + 2*NN;  float* p2 = sm + 3*NN;
    float* md = sm + 4*NN;               // [256][16]
    int*   mi = (int*)(md + 256*16);     // [256][16]
    const int tid = threadIdx.x;
    const int b = blockIdx.x >> 3;
    const int chunk = blockIdx.x & 7;

    if (blockIdx.x == 0) { g_sum[tid] = 0.0; g_sumsq[tid] = 0.0; }

    const float* bx = xyz + (size_t)b * NN * 3;
    for (int i = tid; i < NN; i += 256) {
        float x = bx[i*3], y = bx[i*3+1], z = bx[i*3+2];
        sx[i]=x; sy[i]=y; sz[i]=z;
        p2[i] = __fmaf_rn(z, z, __fmaf_rn(y, y, __fmul_rn(x, x)));
    }
    __syncthreads();

    const int q = chunk*128 + (tid & 127);
    const int half = tid >> 7;
    const float* qp = out + XYZ_OFF + (size_t)(b*SS + q)*3;
    const float qx = qp[0], qy = qp[1], qz = qp[2];
    const float q2 = __fmaf_rn(qz, qz, __fmaf_rn(qy, qy, __fmul_rn(qx, qx)));

    float dk[16]; int ik[16];
    #pragma unroll
    for (int j = 0; j < 16; j++) { dk[j] = 3.4e38f; ik[j] = 0; }

    const int i0 = half * 2048;
    #pragma unroll 2
    for (int i = i0; i < i0 + 2048; i++) {
        float dot = __fmaf_rn(qz, sz[i], __fmaf_rn(qy, sy[i], __fmul_rn(qx, sx[i])));
        float d   = __fmaf_rn(-2.0f, dot, __fadd_rn(q2, p2[i]));
        if (d < dk[15]) {
            dk[15] = d; ik[15] = i;
            #pragma unroll
            for (int j = 15; j > 0; --j) {
                if (dk[j] < dk[j-1]) {
                    float td = dk[j]; dk[j] = dk[j-1]; dk[j-1] = td;
                    int   ti = ik[j]; ik[j] = ik[j-1]; ik[j-1] = ti;
                } else break;
            }
        }
    }
    #pragma unroll
    for (int j = 0; j < 16; j++) { md[tid*16+j] = dk[j]; mi[tid*16+j] = ik[j]; }
    __syncthreads();

    if (tid < 128) {
        int cand[32];
        #pragma unroll
        for (int j = 0; j < 16; j++) {
            cand[j]    = mi[tid*16 + j];
            cand[16+j] = mi[(tid+128)*16 + j];
        }
        const double qdx = (double)qx, qdy = (double)qy, qdz = (double)qz;
        double dd[32];
        #pragma unroll
        for (int j = 0; j < 32; j++) {
            int c = cand[j];
            double ax = (double)sx[c] - qdx;
            double ay = (double)sy[c] - qdy;
            double az = (double)sz[c] - qdz;
            dd[j] = ax*ax + ay*ay + az*az;
        }
        int* dst = g_knn + (size_t)(b*SS + q)*KKNN;
        for (int s = 0; s < 16; s++) {
            int best = s;
            for (int j = s+1; j < 32; j++) {
                if (dd[j] < dd[best] ||
                    (dd[j] == dd[best] && cand[j] < cand[best])) best = j;
            }
            double td = dd[best]; dd[best] = dd[s]; dd[s] = td;
            int    tc = cand[best]; cand[best] = cand[s]; cand[s] = tc;
            dst[s] = tc;
        }
    }
}

// ---------------------------------------------------------------------------
// K3: fused BN statistics (fp64 acc) + per-sample max over K (single gather).
// 256 blocks x 256 thr; block handles 512 rows = 32 samples.
// ---------------------------------------------------------------------------
__global__ __launch_bounds__(256) void k3_stats()
{
    __shared__ int sbase[512];
    const int tid = threadIdx.x;
    const int r0 = blockIdx.x * 512;
    for (int j = tid; j < 512; j += 256) {
        int r = r0 + j;
        int b = r >> 14;
        sbase[j] = (b*NN + g_knn[r]) * DOUT;
    }
    __syncthreads();
    double s0=0, q0=0;
    const int bs0 = blockIdx.x * 32;
    for (int smp = 0; smp < 32; smp++) {
        float mx = -3.4e38f;
        #pragma unroll 4
        for (int k = 0; k < 16; k++) {
            float v = g_h[(size_t)sbase[smp*16 + k] + tid];
            s0 += v;
            q0 = fma((double)v, (double)v, q0);
            mx = fmaxf(mx, v);
        }
        g_hmax[(size_t)(bs0 + smp)*DOUT + tid] = mx;
    }
    atomicAdd(&g_sum[tid],   s0);
    atomicAdd(&g_sumsq[tid], q0);
}

// ---------------------------------------------------------------------------
// K4: affine+ReLU on precomputed per-sample max (scale>=0 fast path);
// generic scale<0 fallback gathers mins from g_h.
// ---------------------------------------------------------------------------
__global__ __launch_bounds__(256) void k4_final(
    const float* __restrict__ gamma, const float* __restrict__ beta,
    float* __restrict__ out)
{
    const int bs = blockIdx.x;
    const int tid = threadIdx.x;
    float mean = (float)(g_sum[tid] * (1.0 / MTOT));
    float var  = (float)(g_sumsq[tid] * (1.0 / MTOT)
                         - (g_sum[tid]*(1.0/MTOT))*(g_sum[tid]*(1.0/MTOT)));
    float rinv = 1.0f / sqrtf(__fadd_rn(var, 1e-5f));
    float ga = gamma[tid], be = beta[tid];
    float scale = ga * rinv;
    float m;
    if (scale >= 0.f) {
        m = g_hmax[(size_t)bs*DOUT + tid];
    } else {
        m = 3.4e38f;
        int b = bs >> 10;
        #pragma unroll
        for (int k = 0; k < 16; k++) {
            int base = (b*NN + g_knn[(size_t)bs*KKNN + k]) * DOUT;
            m = fminf(m, g_h[(size_t)base + tid]);
        }
    }
    float val = __fadd_rn(__fmul_rn(__fmul_rn(ga, __fsub_rn(m, mean)), rinv), be);
    out[(size_t)bs*DOUT + tid] = fmaxf(val, 0.f);
}

// ---------------------------------------------------------------------------
extern "C" void kernel_launch(void* const* d_in, const int* in_sizes, int n_in,
                              void* d_out, int out_size)
{
    (void)in_sizes; (void)n_in; (void)out_size;
    const float* feat  = (const float*)d_in[0];
    const float* xyz   = (const float*)d_in[1];
    const float* W     = (const float*)d_in[2];
    const float* bias  = (const float*)d_in[3];
    const float* gamma = (const float*)d_in[4];
    const float* beta  = (const float*)d_in[5];
    float* out = (float*)d_out;

    const int sm1 = (3*NN + 160) * 4;          // xyz SoA + wpack[2][32] (u64)
    const int sm2 = 4*NN*4 + 256*16*8;         // xyz SoA + p2 + merge buffers
    cudaFuncSetAttribute(k1_fps_gemm, cudaFuncAttributeMaxDynamicSharedMemorySize, sm1);
    cudaFuncSetAttribute(k2_knn,      cudaFuncAttributeMaxDynamicSharedMemorySize, sm2);

    k1_fps_gemm<<<BB + 512, 1024, sm1>>>(feat, xyz, W, bias, out);
    k2_knn<<<64, 256, sm2>>>(xyz, out);
    k3_stats<<<256, 256>>>();
    k4_final<<<BB*SS, 256>>>(gamma, beta, out);
}

// round 11
// speedup vs baseline: 1.0939x; 1.0766x over previous
#include <cuda_runtime.h>

#define BB   8
#define NN   4096
#define DIN  128
#define DOUT 256
#define SS   1024
#define KKNN 16
#define MTOT (BB*SS*KKNN)
#define XYZ_OFF (BB*SS*DOUT)

__device__ float  g_h[BB*NN*DOUT];      // h for all points (33.5MB, L2-resident)
__device__ float  g_hmax[BB*SS*DOUT];   // per-sample max over K (8MB)
__device__ int    g_knn[MTOT];
__device__ double g_sum[DOUT];
__device__ double g_sumsq[DOUT];

// ---- f32x2 packed helpers: per-element round-to-nearest == scalar RN ----
__device__ __forceinline__ unsigned long long pk2(float lo, float hi) {
    unsigned long long r;
    asm("mov.b64 %0, {%1, %2};" : "=l"(r) : "f"(lo), "f"(hi));
    return r;
}
__device__ __forceinline__ void upk2(unsigned long long v, float& lo, float& hi) {
    asm("mov.b64 {%0, %1}, %2;" : "=f"(lo), "=f"(hi) : "l"(v));
}
__device__ __forceinline__ unsigned long long add2(unsigned long long a, unsigned long long b) {
    unsigned long long r;
    asm("add.rn.f32x2 %0, %1, %2;" : "=l"(r) : "l"(a), "l"(b));
    return r;
}
__device__ __forceinline__ unsigned long long mul2(unsigned long long a, unsigned long long b) {
    unsigned long long r;
    asm("mul.rn.f32x2 %0, %1, %2;" : "=l"(r) : "l"(a), "l"(b));
    return r;
}

// ---------------------------------------------------------------------------
// K1: blocks 0..7 = FPS (one batch each); blocks 8.. = exact-fp32 SGEMM.
// FPS math: dx = px + (-lx) [add.rn == sub.rn exactly], d = (dx^2+dy^2)+dz^2
// via f32x2 (per-element RN == scalar). min/argmax on float BITS as unsigned
// (exact for nonneg finite floats) -> IMNMX on alu pipe, f32x2 on fma pipe.
// ---------------------------------------------------------------------------
__global__ __launch_bounds__(1024) void k1_fps_gemm(
    const float* __restrict__ feat, const float* __restrict__ xyz,
    const float* __restrict__ W, const float* __restrict__ bias,
    float* __restrict__ out)
{
    extern __shared__ float sm[];
    const int tid = threadIdx.x;
    const int bid = blockIdx.x;

    if (bid < BB) {
        float* sx = sm;  float* sy = sm + NN;  float* sz = sm + 2*NN;
        unsigned long long* wpack = (unsigned long long*)(sm + 3*NN); // [2][32]

        const float* bx = xyz + (size_t)bid * NN * 3;
        float px[4], py[4], pz[4];
        #pragma unroll
        for (int j = 0; j < 4; j++) {
            int i = j*1024 + tid;
            float x = bx[i*3+0], y = bx[i*3+1], z = bx[i*3+2];
            px[j]=x; py[j]=y; pz[j]=z;
            sx[i]=x; sy[i]=y; sz[i]=z;
        }
        // packed point coords (hoisted)
        const unsigned long long pX01 = pk2(px[0], px[1]), pX23 = pk2(px[2], px[3]);
        const unsigned long long pY01 = pk2(py[0], py[1]), pY23 = pk2(py[2], py[3]);
        const unsigned long long pZ01 = pk2(pz[0], pz[1]), pZ23 = pk2(pz[2], pz[3]);
        unsigned du[4];
        const unsigned INIT = __float_as_uint(1e10f);
        du[0]=INIT; du[1]=INIT; du[2]=INIT; du[3]=INIT;

        __syncthreads();
        float lx = sx[0], ly = sy[0], lz = sz[0];
        if (tid == 0) {
            float* o = out + XYZ_OFF + (size_t)(bid*SS)*3;
            o[0]=lx; o[1]=ly; o[2]=lz;
        }
        const int lane = tid & 31, wid = tid >> 5;

        for (int s = 1; s < SS; s++) {
            // exact negation (sign-bit flip), packed broadcast
            float nlx = __uint_as_float(__float_as_uint(lx) ^ 0x80000000u);
            float nly = __uint_as_float(__float_as_uint(ly) ^ 0x80000000u);
            float nlz = __uint_as_float(__float_as_uint(lz) ^ 0x80000000u);
            unsigned long long Lx = pk2(nlx, nlx), Ly = pk2(nly, nly), Lz = pk2(nlz, nlz);

            // pair A (j=0,1), pair B (j=2,3): d = (dx*dx + dy*dy) + dz*dz
            unsigned long long dxA = add2(pX01, Lx), dyA = add2(pY01, Ly), dzA = add2(pZ01, Lz);
            unsigned long long sA  = add2(add2(mul2(dxA,dxA), mul2(dyA,dyA)), mul2(dzA,dzA));
            unsigned long long dxB = add2(pX23, Lx), dyB = add2(pY23, Ly), dzB = add2(pZ23, Lz);
            unsigned long long sB  = add2(add2(mul2(dxB,dxB), mul2(dyB,dyB)), mul2(dzB,dzB));

            float d0,d1,d2,d3;
            upk2(sA, d0, d1);  upk2(sB, d2, d3);
            // running min on bits (exact: nonneg floats)
            du[0] = min(du[0], __float_as_uint(d0));
            du[1] = min(du[1], __float_as_uint(d1));
            du[2] = min(du[2], __float_as_uint(d2));
            du[3] = min(du[3], __float_as_uint(d3));
            // thread max + first-occurrence index (j ascending = index ascending)
            unsigned bvu = max(max(du[0], du[1]), max(du[2], du[3]));
            unsigned bi  = (du[0]==bvu) ? (unsigned)tid
                         : (du[1]==bvu) ? (unsigned)(1024+tid)
                         : (du[2]==bvu) ? (unsigned)(2048+tid)
                                        : (unsigned)(3072+tid);
            // warp argmax (max value, min index on ties)
            unsigned m   = __reduce_max_sync(0xffffffffu, bvu);
            unsigned cnd = (bvu == m) ? bi : 0xffffffffu;
            unsigned mi  = __reduce_min_sync(0xffffffffu, cnd);
            const int buf = (s & 1) << 5;
            if (lane == 0) wpack[buf + wid] = ((unsigned long long)m << 32) | mi;
            __syncthreads();
            // all warps redundantly reduce the 32 warp winners
            unsigned long long pkv = wpack[buf + lane];
            unsigned v  = (unsigned)(pkv >> 32);
            unsigned ii = (unsigned)pkv;
            unsigned m2 = __reduce_max_sync(0xffffffffu, v);
            unsigned c2 = (v == m2) ? ii : 0xffffffffu;
            unsigned w2 = __reduce_min_sync(0xffffffffu, c2);
            lx = sx[w2]; ly = sy[w2]; lz = sz[w2];
            if (tid == 0) {
                float* o = out + XYZ_OFF + (size_t)(bid*SS + s)*3;
                o[0]=lx; o[1]=ly; o[2]=lz;
            }
        }
    } else {
        // -------- SGEMM: h = feat @ W^T + b, exact fp32 --------
        const int g = bid - BB;
        const int rowBase = (g & 255) * 128;
        const int colBase = (g >> 8) * 128;
        float* As = sm;              // [16][132]
        float* Bs = sm + 16*132;     // [16][132]
        const int l = tid & 31, w = tid >> 5;
        const int tm = l*4, tn = w*4;
        float acc[4][4];
        #pragma unroll
        for (int i=0;i<4;i++)
            #pragma unroll
            for (int j=0;j<4;j++) acc[i][j] = 0.f;

        for (int kc = 0; kc < DIN; kc += 16) {
            if (tid < 512) {
                int r = tid >> 2, q = tid & 3;
                float4 v = *(const float4*)(feat + (size_t)(rowBase + r)*DIN + kc + q*4);
                As[(q*4+0)*132 + r] = v.x;
                As[(q*4+1)*132 + r] = v.y;
                As[(q*4+2)*132 + r] = v.z;
                As[(q*4+3)*132 + r] = v.w;
            } else {
                int t2 = tid - 512; int c = t2 >> 2, q = t2 & 3;
                float4 v = *(const float4*)(W + (size_t)(colBase + c)*DIN + kc + q*4);
                Bs[(q*4+0)*132 + c] = v.x;
                Bs[(q*4+1)*132 + c] = v.y;
                Bs[(q*4+2)*132 + c] = v.z;
                Bs[(q*4+3)*132 + c] = v.w;
            }
            __syncthreads();
            #pragma unroll
            for (int kk = 0; kk < 16; kk++) {
                float4 a  = *(const float4*)(As + kk*132 + tm);
                float4 bb = *(const float4*)(Bs + kk*132 + tn);
                acc[0][0] += a.x*bb.x; acc[0][1] += a.x*bb.y; acc[0][2] += a.x*bb.z; acc[0][3] += a.x*bb.w;
                acc[1][0] += a.y*bb.x; acc[1][1] += a.y*bb.y; acc[1][2] += a.y*bb.z; acc[1][3] += a.y*bb.w;
                acc[2][0] += a.z*bb.x; acc[2][1] += a.z*bb.y; acc[2][2] += a.z*bb.z; acc[2][3] += a.z*bb.w;
                acc[3][0] += a.w*bb.x; acc[3][1] += a.w*bb.y; acc[3][2] += a.w*bb.z; acc[3][3] += a.w*bb.w;
            }
            __syncthreads();
        }
        #pragma unroll
        for (int i = 0; i < 4; i++) {
            int row = rowBase + tm + i;
            float4 o;
            o.x = acc[i][0] + bias[colBase+tn+0];
            o.y = acc[i][1] + bias[colBase+tn+1];
            o.z = acc[i][2] + bias[colBase+tn+2];
            o.w = acc[i][3] + bias[colBase+tn+3];
            *(float4*)(g_h + (size_t)row*DOUT + colBase + tn) = o;
        }
    }
}

// ---------------------------------------------------------------------------
// K2: KNN — fp32 expansion prefilter, fp64 difference-form re-rank (exact).
// ---------------------------------------------------------------------------
__global__ __launch_bounds__(256) void k2_knn(
    const float* __restrict__ xyz, const float* __restrict__ out)
{
    extern __shared__ float sm[];
    float* sx = sm;  float* sy = sm + NN;  float* sz = sm + 2*NN;  float* p2 = sm + 3*NN;
    float* md = sm + 4*NN;               // [256][16]
    int*   mi = (int*)(md + 256*16);     // [256][16]
    const int tid = threadIdx.x;
    const int b = blockIdx.x >> 3;
    const int chunk = blockIdx.x & 7;

    if (blockIdx.x == 0) { g_sum[tid] = 0.0; g_sumsq[tid] = 0.0; }

    const float* bx = xyz + (size_t)b * NN * 3;
    for (int i = tid; i < NN; i += 256) {
        float x = bx[i*3], y = bx[i*3+1], z = bx[i*3+2];
        sx[i]=x; sy[i]=y; sz[i]=z;
        p2[i] = __fmaf_rn(z, z, __fmaf_rn(y, y, __fmul_rn(x, x)));
    }
    __syncthreads();

    const int q = chunk*128 + (tid & 127);
    const int half = tid >> 7;
    const float* qp = out + XYZ_OFF + (size_t)(b*SS + q)*3;
    const float qx = qp[0], qy = qp[1], qz = qp[2];
    const float q2 = __fmaf_rn(qz, qz, __fmaf_rn(qy, qy, __fmul_rn(qx, qx)));

    float dk[16]; int ik[16];
    #pragma unroll
    for (int j = 0; j < 16; j++) { dk[j] = 3.4e38f; ik[j] = 0; }

    const int i0 = half * 2048;
    #pragma unroll 2
    for (int i = i0; i < i0 + 2048; i++) {
        float dot = __fmaf_rn(qz, sz[i], __fmaf_rn(qy, sy[i], __fmul_rn(qx, sx[i])));
        float d   = __fmaf_rn(-2.0f, dot, __fadd_rn(q2, p2[i]));
        if (d < dk[15]) {
            dk[15] = d; ik[15] = i;
            #pragma unroll
            for (int j = 15; j > 0; --j) {
                if (dk[j] < dk[j-1]) {
                    float td = dk[j]; dk[j] = dk[j-1]; dk[j-1] = td;
                    int   ti = ik[j]; ik[j] = ik[j-1]; ik[j-1] = ti;
                } else break;
            }
        }
    }
    #pragma unroll
    for (int j = 0; j < 16; j++) { md[tid*16+j] = dk[j]; mi[tid*16+j] = ik[j]; }
    __syncthreads();

    if (tid < 128) {
        int cand[32];
        #pragma unroll
        for (int j = 0; j < 16; j++) {
            cand[j]    = mi[tid*16 + j];
            cand[16+j] = mi[(tid+128)*16 + j];
        }
        const double qdx = (double)qx, qdy = (double)qy, qdz = (double)qz;
        double dd[32];
        #pragma unroll
        for (int j = 0; j < 32; j++) {
            int c = cand[j];
            double ax = (double)sx[c] - qdx;
            double ay = (double)sy[c] - qdy;
            double az = (double)sz[c] - qdz;
            dd[j] = ax*ax + ay*ay + az*az;
        }
        int* dst = g_knn + (size_t)(b*SS + q)*KKNN;
        for (int s = 0; s < 16; s++) {
            int best = s;
            for (int j = s+1; j < 32; j++) {
                if (dd[j] < dd[best] ||
                    (dd[j] == dd[best] && cand[j] < cand[best])) best = j;
            }
            double td = dd[best]; dd[best] = dd[s]; dd[s] = td;
            int    tc = cand[best]; cand[best] = cand[s]; cand[s] = tc;
            dst[s] = tc;
        }
    }
}

// ---------------------------------------------------------------------------
// K3: fused BN statistics (fp64 acc) + per-sample max over K (single gather).
// ---------------------------------------------------------------------------
__global__ __launch_bounds__(256) void k3_stats()
{
    __shared__ int sbase[512];
    const int tid = threadIdx.x;
    const int r0 = blockIdx.x * 512;
    for (int j = tid; j < 512; j += 256) {
        int r = r0 + j;
        int b = r >> 14;
        sbase[j] = (b*NN + g_knn[r]) * DOUT;
    }
    __syncthreads();
    double s0=0, q0=0;
    const int bs0 = blockIdx.x * 32;
    for (int smp = 0; smp < 32; smp++) {
        float mx = -3.4e38f;
        #pragma unroll 4
        for (int k = 0; k < 16; k++) {
            float v = g_h[(size_t)sbase[smp*16 + k] + tid];
            s0 += v;
            q0 = fma((double)v, (double)v, q0);
            mx = fmaxf(mx, v);
        }
        g_hmax[(size_t)(bs0 + smp)*DOUT + tid] = mx;
    }
    atomicAdd(&g_sum[tid],   s0);
    atomicAdd(&g_sumsq[tid], q0);
}

// ---------------------------------------------------------------------------
// K4: affine+ReLU on precomputed per-sample max (scale>=0 fast path).
// ---------------------------------------------------------------------------
__global__ __launch_bounds__(256) void k4_final(
    const float* __restrict__ gamma, const float* __restrict__ beta,
    float* __restrict__ out)
{
    const int bs = blockIdx.x;
    const int tid = threadIdx.x;
    float mean = (float)(g_sum[tid] * (1.0 / MTOT));
    float var  = (float)(g_sumsq[tid] * (1.0 / MTOT)
                         - (g_sum[tid]*(1.0/MTOT))*(g_sum[tid]*(1.0/MTOT)));
    float rinv = 1.0f / sqrtf(__fadd_rn(var, 1e-5f));
    float ga = gamma[tid], be = beta[tid];
    float scale = ga * rinv;
    float m;
    if (scale >= 0.f) {
        m = g_hmax[(size_t)bs*DOUT + tid];
    } else {
        m = 3.4e38f;
        int b = bs >> 10;
        #pragma unroll
        for (int k = 0; k < 16; k++) {
            int base = (b*NN + g_knn[(size_t)bs*KKNN + k]) * DOUT;
            m = fminf(m, g_h[(size_t)base + tid]);
        }
    }
    float val = __fadd_rn(__fmul_rn(__fmul_rn(ga, __fsub_rn(m, mean)), rinv), be);
    out[(size_t)bs*DOUT + tid] = fmaxf(val, 0.f);
}

// ---------------------------------------------------------------------------
extern "C" void kernel_launch(void* const* d_in, const int* in_sizes, int n_in,
                              void* d_out, int out_size)
{
    (void)in_sizes; (void)n_in; (void)out_size;
    const float* feat  = (const float*)d_in[0];
    const float* xyz   = (const float*)d_in[1];
    const float* W     = (const float*)d_in[2];
    const float* bias  = (const float*)d_in[3];
    const float* gamma = (const float*)d_in[4];
    const float* beta  = (const float*)d_in[5];
    float* out = (float*)d_out;

    const int sm1 = (3*NN + 160) * 4;          // xyz SoA + wpack[2][32] (u64)
    const int sm2 = 4*NN*4 + 256*16*8;         // xyz SoA + p2 + merge buffers
    cudaFuncSetAttribute(k1_fps_gemm, cudaFuncAttributeMaxDynamicSharedMemorySize, sm1);
    cudaFuncSetAttribute(k2_knn,      cudaFuncAttributeMaxDynamicSharedMemorySize, sm2);

    k1_fps_gemm<<<BB + 512, 1024, sm1>>>(feat, xyz, W, bias, out);
    k2_knn<<<64, 256, sm2>>>(xyz, out);
    k3_stats<<<256, 256>>>();
    k4_final<<<BB*SS, 256>>>(gamma, beta, out);
}